// round 2
// baseline (speedup 1.0000x reference)
#include <cuda_runtime.h>

// SubGraphAvgPool: out[b,g,d] = mean(h[b,g,d], h[b,4g+1,d], h[b,4g+2,d], h[b,4g+3,d], h[b,4g+4,d])
// B=16, N=8193, D=512, m=4 -> G=2048. Output [16, 2048, 512] fp32.
//
// One CTA per (b,g); 128 threads; each thread handles one float4 of D (128*4=512).
// 5 independent coalesced LDG.128 per thread + 1 STG.128. Pure HBM streaming.

static constexpr int B = 16;
static constexpr long long N = 8193;
static constexpr int D = 512;
static constexpr int G = 2048;
static constexpr int DV = D / 4;  // 128 float4 per row

__global__ __launch_bounds__(128, 8)
void subgraph_avgpool_kernel(const float* __restrict__ h, float* __restrict__ out) {
    const int bg = blockIdx.x;          // 0 .. B*G-1
    const int g  = bg & (G - 1);        // G = 2048 = 2^11
    const int b  = bg >> 11;
    const int dv = threadIdx.x;         // 0 .. 127

    const float4* __restrict__ hp =
        reinterpret_cast<const float4*>(h) + (long long)b * (N * DV) + dv;

    // g-node row
    const float4 a0 = hp[(long long)g * DV];
    // 4 consecutive child rows 4g+1 .. 4g+4
    const long long r = (long long)(4 * g + 1) * DV;
    const float4 a1 = hp[r];
    const float4 a2 = hp[r + DV];
    const float4 a3 = hp[r + 2 * DV];
    const float4 a4 = hp[r + 3 * DV];

    float4 s;
    s.x = (a0.x + a1.x + a2.x + a3.x + a4.x) * 0.2f;
    s.y = (a0.y + a1.y + a2.y + a3.y + a4.y) * 0.2f;
    s.z = (a0.z + a1.z + a2.z + a3.z + a4.z) * 0.2f;
    s.w = (a0.w + a1.w + a2.w + a3.w + a4.w) * 0.2f;

    reinterpret_cast<float4*>(out)[(long long)bg * DV + dv] = s;
}

extern "C" void kernel_launch(void* const* d_in, const int* in_sizes, int n_in,
                              void* d_out, int out_size) {
    const float* h = (const float*)d_in[0];
    float* out = (float*)d_out;
    subgraph_avgpool_kernel<<<B * G, 128>>>(h, out);
}

// round 3
// speedup vs baseline: 1.0501x; 1.0501x over previous
#include <cuda_runtime.h>

// SubGraphAvgPool: out[b,g,d] = mean(h[b,g,d], h[b,4g+1..4g+4,d]),  B=16, N=8193, D=512, G=2048.
//
// One CTA per (b,g); 128 threads; one float4 per thread per row.
// Cache-hint policy:
//   - g-node row load:      __ldcs (last use of that row -> evict_first)
//   - child rows, g >= 512: __ldcs (rows >= 2049, single-use stream)
//   - child rows, g <  512: default (rows 1..2048, re-read later as g-nodes -> keep in L2)
//   - output store:         __stcs (write-once, never re-read)

static constexpr int B = 16;
static constexpr long long N = 8193;
static constexpr int D = 512;
static constexpr int G = 2048;
static constexpr int DV = D / 4;  // 128 float4 per row

__global__ __launch_bounds__(128, 8)
void subgraph_avgpool_kernel(const float* __restrict__ h, float* __restrict__ out) {
    const int bg = blockIdx.x;          // 0 .. B*G-1
    const int g  = bg & (G - 1);        // G = 2048 = 2^11
    const int b  = bg >> 11;
    const int dv = threadIdx.x;         // 0 .. 127

    const float4* __restrict__ hp =
        reinterpret_cast<const float4*>(h) + (long long)b * (N * DV) + dv;

    // g-node row: last use of row g -> streaming load
    const float4 a0 = __ldcs(hp + (long long)g * DV);

    const float4* p = hp + (long long)(4 * g + 1) * DV;
    float4 a1, a2, a3, a4;
    if (g >= 512) {
        // child rows >= 2049: single-use, evict-first
        a1 = __ldcs(p);
        a2 = __ldcs(p + DV);
        a3 = __ldcs(p + 2 * DV);
        a4 = __ldcs(p + 3 * DV);
    } else {
        // child rows 1..2048: will be re-read later as g-node rows -> keep cached
        a1 = __ldg(p);
        a2 = __ldg(p + DV);
        a3 = __ldg(p + 2 * DV);
        a4 = __ldg(p + 3 * DV);
    }

    float4 s;
    s.x = (a0.x + a1.x + a2.x + a3.x + a4.x) * 0.2f;
    s.y = (a0.y + a1.y + a2.y + a3.y + a4.y) * 0.2f;
    s.z = (a0.z + a1.z + a2.z + a3.z + a4.z) * 0.2f;
    s.w = (a0.w + a1.w + a2.w + a3.w + a4.w) * 0.2f;

    __stcs(reinterpret_cast<float4*>(out) + (long long)bg * DV + dv, s);
}

extern "C" void kernel_launch(void* const* d_in, const int* in_sizes, int n_in,
                              void* d_out, int out_size) {
    const float* h = (const float*)d_in[0];
    float* out = (float*)d_out;
    subgraph_avgpool_kernel<<<B * G, 128>>>(h, out);
}